// round 14
// baseline (speedup 1.0000x reference)
#include <cuda_runtime.h>
#include <math.h>
#include <stdint.h>

// ---------------- problem constants ----------------
#define BB 4
#define LL 5
#define HW 1024          // HS*WS
#define CC 256
#define MM 8
#define DD 32
#define TT 2
#define II 256           // M*D
#define NTOK (BB*LL*HW)  // 20480
#define TOKELEMS (NTOK*CC)

// K-dim permutation (within 16-groups): pos(k) = (k&~15) | ((k&3)<<2) | ((k>>2)&3)
// A thread's four fragment elements (k, k+4, k+8, k+12) become one float4.
#define PERM16(k) ((((k) & 3) << 2) | (((k) >> 2) & 3))

// ---------------- scratch (static device globals) ----------------
__device__ __align__(16) float g_xn[TOKELEMS];      // tf32 LN output, K16-permuted
__device__ __align__(16) float g_q [TOKELEMS];      // fp32 q (plain layout)
__device__ __align__(16) float g_k [TOKELEMS];      // tf32 k (plain layout)
__device__ __align__(16) float g_v [TOKELEMS];      // tf32 v (plain layout)
__device__ __align__(16) float g_kp[2*TOKELEMS];    // transformed K, ti=0/1
__device__ __align__(16) float g_vp[2*TOKELEMS];    // transformed V, ti=0/1
__device__ __align__(16) float g_ao[TOKELEMS];      // tf32 attn out, K16-permuted
__device__ __align__(16) float g_wq[TT*CC*II];      // tf32 W^T [t][n][pos16(k)]
__device__ __align__(16) float g_wk[TT*CC*II];
__device__ __align__(16) float g_wv[TT*CC*II];
__device__ __align__(16) float g_wa[TT*II*CC];
__device__ __align__(16) float g_rat[4*MM*DD*DD];   // tf32 RA*scale  [e][m][p][q]
__device__ __align__(16) float g_rmt[4*MM*DD*DD];   // tf32 RM^T      [e][m][o][p]

// ---------------- helpers ----------------
__device__ __forceinline__ unsigned f2tf(float f) {
    unsigned u;
    asm("cvt.rna.tf32.f32 %0, %1;" : "=r"(u) : "f"(f));
    return u;
}
__device__ __forceinline__ float f2tf_f(float f) { return __uint_as_float(f2tf(f)); }

__device__ __forceinline__ void mma_tf32(float c[4],
                                         unsigned a0, unsigned a1, unsigned a2, unsigned a3,
                                         unsigned b0, unsigned b1)
{
    asm volatile(
        "mma.sync.aligned.m16n8k8.row.col.f32.tf32.tf32.f32 "
        "{%0,%1,%2,%3}, {%4,%5,%6,%7}, {%8,%9}, {%0,%1,%2,%3};"
        : "+f"(c[0]), "+f"(c[1]), "+f"(c[2]), "+f"(c[3])
        : "r"(a0), "r"(a1), "r"(a2), "r"(a3), "r"(b0), "r"(b1));
}

__device__ __forceinline__ void cpa16(float* dst, const float* src) {
    unsigned d = (unsigned)__cvta_generic_to_shared(dst);
    asm volatile("cp.async.cg.shared.global [%0], [%1], 16;" :: "r"(d), "l"(src));
}
__device__ __forceinline__ void cpa_commit() {
    asm volatile("cp.async.commit_group;" ::: "memory");
}
template <int N> __device__ __forceinline__ void cpa_wait() {
    asm volatile("cp.async.wait_group %0;" :: "n"(N) : "memory");
}

// =====================================================================
// Kernel 0 (merged prep):
//   blocks [0,512)    : weight transpose + K16-perm + tf32 round
//   blocks [512,544)  : relation-matrix prep
//   blocks [544,3104) : LayerNorm (smem row-buffer, permuted store)
// =====================================================================
__global__ __launch_bounds__(256) void k_prep(const float* __restrict__ Wq,
                                              const float* __restrict__ Wk,
                                              const float* __restrict__ Wv,
                                              const float* __restrict__ Wa,
                                              const float* __restrict__ ra,
                                              const float* __restrict__ rm,
                                              const float* __restrict__ x,
                                              const float* __restrict__ lw,
                                              const float* __restrict__ lb)
{
    __shared__ float tile[32][33];
    __shared__ float slw[256], slb[256];
    __shared__ __align__(16) float rbuf[8][272];
    int bx  = blockIdx.x;
    int tid = threadIdx.x;

    if (bx < 512) {
        // ---- weight transpose [t][k][n] -> [t][n][pos16(k)], tf32 round ----
        int tsr  = bx >> 7;            // 0..3: Wq, Wk, Wv, Wa
        int tt   = (bx >> 6) & 1;      // type slice
        int tl   = bx & 63;            // 8x8 tiles of 32x32
        int k0   = (tl >> 3) << 5;
        int n0   = (tl & 7) << 5;
        const float* src;
        float* dst;
        switch (tsr) {
            case 0: src = Wq; dst = g_wq; break;
            case 1: src = Wk; dst = g_wk; break;
            case 2: src = Wv; dst = g_wv; break;
            default: src = Wa; dst = g_wa; break;
        }
        src += (size_t)tt * 65536;
        dst += (size_t)tt * 65536;

        int c  = tid & 31;
        int r0 = tid >> 5;
        #pragma unroll
        for (int rr = r0; rr < 32; rr += 8)
            tile[rr][c] = src[(size_t)(k0 + rr) * 256 + n0 + c];
        __syncthreads();
        int pc = (c & 16) | PERM16(c & 15);
        #pragma unroll
        for (int rr = r0; rr < 32; rr += 8)
            dst[(size_t)(n0 + rr) * 256 + k0 + pc] = f2tf_f(tile[c][rr]);
        return;
    }

    if (bx < 544) {
        // ---- relation prep: 32 blocks = (e=4, m=8) ----
        int e = (bx - 512) >> 3;
        int m = (bx - 512) & 7;
        size_t base = (size_t)(e * MM + m) * 1024;

        #pragma unroll
        for (int i = tid; i < 1024; i += 256)
            g_rat[base + i] = f2tf_f(0.17677669529663687f * ra[base + i]);

        #pragma unroll
        for (int i = tid; i < 1024; i += 256)
            tile[(i >> 5) & 31][i & 31] = rm[base + i];
        __syncthreads();
        #pragma unroll
        for (int i = tid; i < 1024; i += 256) {
            int o = i >> 5, p = i & 31;
            g_rmt[base + i] = f2tf_f(tile[p][o]);
        }
        return;
    }

    // ---- LayerNorm: one warp per token, K16-permuted store ----
    int warp = tid >> 5;
    int lane = tid & 31;
    int tok  = ((bx - 544) << 3) + warp;

    slw[tid] = lw[tid];
    slb[tid] = lb[tid];
    __syncthreads();

    // stage row (original order) into per-warp smem buffer
    const float4* xr = reinterpret_cast<const float4*>(x + (size_t)tok * CC);
    float4 v0 = xr[lane];
    float4 v1 = xr[lane + 32];
    float* rb = &rbuf[warp][0];
    reinterpret_cast<float4*>(rb)[lane]      = v0;
    reinterpret_cast<float4*>(rb)[lane + 32] = v1;
    __syncwarp();

    // gather this thread's 8 permuted values: pos quads Q=lane, lane+32
    //   g = Q>>2 (16-group), sub = Q&3; orig k for slot i: k = g*16 + 4i + sub
    float val[2][4], wv[2][4], bv[2][4];
    float s = 0.f, sq = 0.f;
    #pragma unroll
    for (int h = 0; h < 2; ++h) {
        int g   = (lane >> 2) + (h << 3);
        int sub = lane & 3;
        #pragma unroll
        for (int i = 0; i < 4; ++i) {
            int k = g * 16 + (i << 2) + sub;
            float xv = rb[k];
            val[h][i] = xv;
            wv[h][i]  = slw[k];
            bv[h][i]  = slb[k];
            s  += xv;
            sq += xv * xv;
        }
    }
    #pragma unroll
    for (int off = 16; off >= 1; off >>= 1) {
        s  += __shfl_xor_sync(0xffffffffu, s,  off);
        sq += __shfl_xor_sync(0xffffffffu, sq, off);
    }
    float mean = s * (1.0f / 256.0f);
    float var  = sq * (1.0f / 256.0f) - mean * mean;
    float rstd = rsqrtf(var + 1e-5f);

    float4 o0, o1;
    o0.x = f2tf_f((val[0][0] - mean) * rstd * wv[0][0] + bv[0][0]);
    o0.y = f2tf_f((val[0][1] - mean) * rstd * wv[0][1] + bv[0][1]);
    o0.z = f2tf_f((val[0][2] - mean) * rstd * wv[0][2] + bv[0][2]);
    o0.w = f2tf_f((val[0][3] - mean) * rstd * wv[0][3] + bv[0][3]);
    o1.x = f2tf_f((val[1][0] - mean) * rstd * wv[1][0] + bv[1][0]);
    o1.y = f2tf_f((val[1][1] - mean) * rstd * wv[1][1] + bv[1][1]);
    o1.z = f2tf_f((val[1][2] - mean) * rstd * wv[1][2] + bv[1][2]);
    o1.w = f2tf_f((val[1][3] - mean) * rstd * wv[1][3] + bv[1][3]);

    float4* orow = reinterpret_cast<float4*>(g_xn + (size_t)tok * CC);
    orow[lane]      = o0;
    orow[lane + 32] = o1;
}

// =====================================================================
// tf32 GEMM tile v3: 128 threads = 2x2 warps of 64x64, BK=16 double
// buffer, stride-16 smem (no pad, conflict-free LDS.128 via PERM16).
// A: [m][pos16(k)] (lda=256).  Wt: [n][pos16(k)] (ld=256).
// Out[128x128] = A * Wt^T + bias.  smem = 32KB, 2 CTAs/SM.
// =====================================================================
#define TSZ3 (128 * 16)     // 2048 floats = 8KB per tile stage

__device__ __forceinline__ void gemm_tf32(const float* __restrict__ A,
                                          const float* __restrict__ Wt,
                                          const float* __restrict__ bias,
                                          float* __restrict__ Out,
                                          int m0, int ncol0, int rnd)
{
    __shared__ __align__(16) float As[2 * TSZ3];
    __shared__ __align__(16) float Bs[2 * TSZ3];

    const int tid  = threadIdx.x;       // 0..127
    const int lane = tid & 31;
    const int warp = tid >> 5;          // 0..3
    const int wm = (warp >> 1) << 6;    // 0, 64
    const int wn = (warp & 1)  << 6;    // 0, 64

    // loader: 512 float4 per tile / 128 threads = 4 chunks each
    int lrow[4], lc4[4];
    #pragma unroll
    for (int it = 0; it < 4; ++it) {
        int pos = tid + (it << 7);
        lrow[it] = pos >> 2;  lc4[it] = (pos & 3) << 2;
    }

    float acc[4][8][4];
    #pragma unroll
    for (int mt = 0; mt < 4; ++mt)
        #pragma unroll
        for (int nt = 0; nt < 8; ++nt)
            #pragma unroll
            for (int r = 0; r < 4; ++r) acc[mt][nt][r] = 0.0f;

    #pragma unroll
    for (int it = 0; it < 4; ++it) {
        cpa16(As + lrow[it] * 16 + lc4[it],
              A  + (size_t)(m0 + lrow[it]) * 256 + lc4[it]);
        cpa16(Bs + lrow[it] * 16 + lc4[it],
              Wt + (size_t)(ncol0 + lrow[it]) * 256 + lc4[it]);
    }
    cpa_commit();

    for (int ch = 0; ch < 16; ++ch) {
        int buf = ch & 1;
        if (ch < 15) {
            int kc = (ch + 1) << 4;
            float* Asn = As + (buf ^ 1) * TSZ3;
            float* Bsn = Bs + (buf ^ 1) * TSZ3;
            #pragma unroll
            for (int it = 0; it < 4; ++it) {
                cpa16(Asn + lrow[it] * 16 + lc4[it],
                      A  + (size_t)(m0 + lrow[it]) * 256 + kc + lc4[it]);
                cpa16(Bsn + lrow[it] * 16 + lc4[it],
                      Wt + (size_t)(ncol0 + lrow[it]) * 256 + kc + lc4[it]);
            }
            cpa_commit();
            cpa_wait<1>();
        } else {
            cpa_wait<0>();
        }
        __syncthreads();

        const float* Asb = As + buf * TSZ3;
        const float* Bsb = Bs + buf * TSZ3;
        int kq = (lane & 3) << 2;

        // one LDS.128 per fragment row covers BOTH k-steps (x,y | z,w)
        float4 af[4][2];
        float4 bf[8];
        #pragma unroll
        for (int mt = 0; mt < 4; ++mt) {
            int row = wm + (mt << 4) + (lane >> 2);
            af[mt][0] = *reinterpret_cast<const float4*>(Asb + row * 16 + kq);
            af[mt][1] = *reinterpret_cast<const float4*>(Asb + (row + 8) * 16 + kq);
        }
        #pragma unroll
        for (int nt = 0; nt < 8; ++nt) {
            int row = wn + (nt << 3) + (lane >> 2);
            bf[nt] = *reinterpret_cast<const float4*>(Bsb + row * 16 + kq);
        }
        // ks = 0 (k, k+4)
        #pragma unroll
        for (int mt = 0; mt < 4; ++mt)
            #pragma unroll
            for (int nt = 0; nt < 8; ++nt)
                mma_tf32(acc[mt][nt],
                         __float_as_uint(af[mt][0].x), __float_as_uint(af[mt][1].x),
                         __float_as_uint(af[mt][0].y), __float_as_uint(af[mt][1].y),
                         __float_as_uint(bf[nt].x),    __float_as_uint(bf[nt].y));
        // ks = 1 (k+8, k+12)
        #pragma unroll
        for (int mt = 0; mt < 4; ++mt)
            #pragma unroll
            for (int nt = 0; nt < 8; ++nt)
                mma_tf32(acc[mt][nt],
                         __float_as_uint(af[mt][0].z), __float_as_uint(af[mt][1].z),
                         __float_as_uint(af[mt][0].w), __float_as_uint(af[mt][1].w),
                         __float_as_uint(bf[nt].z),    __float_as_uint(bf[nt].w));
        __syncthreads();
    }

    #pragma unroll
    for (int mt = 0; mt < 4; ++mt) {
        int mrow = m0 + wm + (mt << 4) + (lane >> 2);
        #pragma unroll
        for (int nt = 0; nt < 8; ++nt) {
            int nc = ncol0 + wn + (nt << 3) + ((lane & 3) << 1);
            float b0 = bias[nc], b1 = bias[nc + 1];
            float2 r0, r1;
            r0.x = acc[mt][nt][0] + b0; r0.y = acc[mt][nt][1] + b1;
            r1.x = acc[mt][nt][2] + b0; r1.y = acc[mt][nt][3] + b1;
            if (rnd) {
                r0.x = f2tf_f(r0.x); r0.y = f2tf_f(r0.y);
                r1.x = f2tf_f(r1.x); r1.y = f2tf_f(r1.y);
            }
            *reinterpret_cast<float2*>(Out + (size_t)mrow * 256 + nc)       = r0;
            *reinterpret_cast<float2*>(Out + (size_t)(mrow + 8) * 256 + nc) = r1;
        }
    }
}

// =====================================================================
// Kernel 2: q/k/v projection. grid = (8 mtiles, 6, 20 bl), 128 threads.
// =====================================================================
__global__ __launch_bounds__(128) void k_gemm_qkv(const float* __restrict__ pe,
                                                  const float* __restrict__ bq,
                                                  const float* __restrict__ bk,
                                                  const float* __restrict__ bv)
{
    int bl = blockIdx.z;
    int t  = (int)pe[(size_t)bl * 3072 + 2];
    int sel   = blockIdx.y >> 1;
    int ncol0 = (blockIdx.y & 1) << 7;

    const float* W;
    const float* bias;
    float* out;
    int rnd;
    if (sel == 0)      { W = g_wq; bias = bq; out = g_q; rnd = 0; }
    else if (sel == 1) { W = g_wk; bias = bk; out = g_k; rnd = 1; }
    else               { W = g_wv; bias = bv; out = g_v; rnd = 1; }

    gemm_tf32(g_xn + (size_t)bl * HW * CC,
              W + (size_t)t * CC * II,
              bias + (size_t)t * II,
              out + (size_t)bl * HW * II,
              blockIdx.x << 7, ncol0, rnd);
}

// =====================================================================
// Kernel 2b: relation transform (unchanged — proven). grid = (320, 8).
// =====================================================================
__global__ __launch_bounds__(256) void k_xform(const float* __restrict__ pe)
{
    __shared__ __align__(16) float sra[2][32 * 36];
    __shared__ __align__(16) float srm[2][32 * 36];

    int tid  = threadIdx.x;
    int lane = tid & 31;
    int wid  = tid >> 5;
    int m    = blockIdx.y;
    int tok0 = (int)blockIdx.x << 6;
    int bl   = tok0 >> 10;
    int tj   = (int)pe[(size_t)bl * 3072 + 2];

    #pragma unroll
    for (int c = 0; c < 4; ++c) {
        int chunk = tid + (c << 8);
        int mat   = chunk >> 8;
        int off   = chunk & 255;
        int row   = off >> 3;
        int col4  = (off & 7) << 2;
        int ti    = mat & 1;
        int kind  = mat >> 1;
        const float* src = (kind ? g_rmt : g_rat)
                         + (((size_t)((ti * 2 + tj) * MM + m)) << 10) + off * 4;
        float* dst = (kind ? &srm[ti][0] : &sra[ti][0]) + row * 36 + col4;
        cpa16(dst, src);
    }
    cpa_commit();
    cpa_wait<0>();
    __syncthreads();

    int side = wid >> 2;
    int wmt  = wid & 3;
    const float* srcg = side ? g_v : g_k;
    float* dstg       = side ? g_vp : g_kp;

    int arow = tok0 + (wmt << 4) + (lane >> 2);
    const float* abase = srcg + (size_t)arow * 256 + (m << 5) + (lane & 3);
    unsigned af[4][4];
    #pragma unroll
    for (int ks = 0; ks < 4; ++ks) {
        af[ks][0] = __float_as_uint(abase[ks * 8]);
        af[ks][1] = __float_as_uint(abase[8 * 256 + ks * 8]);
        af[ks][2] = __float_as_uint(abase[ks * 8 + 4]);
        af[ks][3] = __float_as_uint(abase[8 * 256 + ks * 8 + 4]);
    }

    float acc[2][4][4];
    #pragma unroll
    for (int ti = 0; ti < 2; ++ti)
        #pragma unroll
        for (int nt = 0; nt < 4; ++nt)
            #pragma unroll
            for (int r = 0; r < 4; ++r) acc[ti][nt][r] = 0.0f;

    #pragma unroll
    for (int ks = 0; ks < 4; ++ks) {
        int k0 = (ks << 3) + (lane & 3);
        #pragma unroll
        for (int nt = 0; nt < 4; ++nt) {
            int br = (nt << 3) + (lane >> 2);
            #pragma unroll
            for (int ti = 0; ti < 2; ++ti) {
                const float* B = side ? &srm[ti][0] : &sra[ti][0];
                unsigned b0 = __float_as_uint(B[br * 36 + k0]);
                unsigned b1 = __float_as_uint(B[br * 36 + k0 + 4]);
                mma_tf32(acc[ti][nt], af[ks][0], af[ks][1], af[ks][2], af[ks][3],
                         b0, b1);
            }
        }
    }

    #pragma unroll
    for (int ti = 0; ti < 2; ++ti) {
        float* Ob = dstg + (size_t)ti * TOKELEMS;
        #pragma unroll
        for (int nt = 0; nt < 4; ++nt) {
            int col = (m << 5) + (nt << 3) + ((lane & 3) << 1);
            int r0  = tok0 + (wmt << 4) + (lane >> 2);
            float2 w0, w1;
            w0.x = acc[ti][nt][0]; w0.y = acc[ti][nt][1];
            w1.x = acc[ti][nt][2]; w1.y = acc[ti][nt][3];
            *reinterpret_cast<float2*>(Ob + (size_t)r0 * 256 + col)       = w0;
            *reinterpret_cast<float2*>(Ob + (size_t)(r0 + 8) * 256 + col) = w1;
        }
    }
}

// =====================================================================
// Kernel 3: attention. One (b,m,hw) per warp, grid = 4096.
// Output stored with K16-permuted columns (feeds ao GEMM).
// =====================================================================
__global__ __launch_bounds__(256) void k_attn(const int*   __restrict__ mask,
                                              const float* __restrict__ pe)
{
    __shared__ int ts_s[LL];

    int tid  = threadIdx.x;
    int lane = tid & 31;
    int w    = tid >> 5;
    int bidx = blockIdx.x;
    int hw   = ((bidx & 127) << 3) + w;
    int m    = (bidx >> 7) & 7;
    int b    = bidx >> 10;

    if (tid < LL) ts_s[tid] = (int)pe[(size_t)(b * LL + tid) * 3072 + 2];
    __syncthreads();

    int base_off = (m << 5) + lane;
    int tokbase  = ((b * LL) << 10) + hw;
    float qreg[LL], kp0[LL], kp1[LL], vp0[LL], vp1[LL];
    #pragma unroll
    for (int j = 0; j < LL; ++j) {
        unsigned off = (unsigned)(tokbase + (j << 10)) * 256u + (unsigned)base_off;
        qreg[j] = g_q [off];
        kp0[j]  = g_kp[off];
        kp1[j]  = g_kp[(size_t)off + (size_t)TOKELEMS];
        vp0[j]  = g_vp[off];
        vp1[j]  = g_vp[(size_t)off + (size_t)TOKELEMS];
    }

    float att[LL][LL];
    #pragma unroll
    for (int i = 0; i < LL; ++i) {
        float q = qreg[i];
        if (ts_s[i]) {
            #pragma unroll
            for (int j = 0; j < LL; ++j) att[i][j] = q * kp1[j];
        } else {
            #pragma unroll
            for (int j = 0; j < LL; ++j) att[i][j] = q * kp0[j];
        }
        #pragma unroll
        for (int j = 0; j < LL; ++j) {
            float part = att[i][j];
            part += __shfl_xor_sync(0xffffffffu, part, 16);
            part += __shfl_xor_sync(0xffffffffu, part, 8);
            part += __shfl_xor_sync(0xffffffffu, part, 4);
            part += __shfl_xor_sync(0xffffffffu, part, 2);
            part += __shfl_xor_sync(0xffffffffu, part, 1);
            att[i][j] = part;
        }
    }

    // K16-permuted output column for the ao GEMM
    int plane = (lane & 16) | PERM16(lane & 15);
    int obase = (m << 5) + plane;

    const int* mrow = mask + ((size_t)(b << 10) + hw) * 25;
    #pragma unroll
    for (int i = 0; i < LL; ++i) {
        float mx = -1e30f;
        #pragma unroll
        for (int j = 0; j < LL; ++j) {
            if (mrow[i * 5 + j] == 0) att[i][j] = -1e9f;
            mx = fmaxf(mx, att[i][j]);
        }
        float s = 0.f;
        #pragma unroll
        for (int j = 0; j < LL; ++j) {
            float e = __expf(att[i][j] - mx);
            att[i][j] = e;
            s += e;
        }
        float inv = 1.0f / s;
        float o = 0.f;
        if (ts_s[i]) {
            #pragma unroll
            for (int j = 0; j < LL; ++j) o = fmaf(att[i][j], vp1[j], o);
        } else {
            #pragma unroll
            for (int j = 0; j < LL; ++j) o = fmaf(att[i][j], vp0[j], o);
        }
        unsigned tok = (unsigned)(tokbase + (i << 10));
        g_ao[(size_t)tok * 256 + obase] = f2tf_f(o * inv);
    }
}

// =====================================================================
// Kernel 4: output projection + bias -> final output. grid = (8,2,20)
// =====================================================================
__global__ __launch_bounds__(128) void k_gemm_ao(const float* __restrict__ pe,
                                                 const float* __restrict__ ba,
                                                 float* __restrict__ out)
{
    int bl = blockIdx.z;
    int t  = (int)pe[(size_t)bl * 3072 + 2];
    gemm_tf32(g_ao + (size_t)bl * HW * II,
              g_wa + (size_t)t * II * CC,
              ba + (size_t)t * CC,
              out + (size_t)bl * HW * CC,
              blockIdx.x << 7, (blockIdx.y & 1) << 7, 0);
}

// =====================================================================
extern "C" void kernel_launch(void* const* d_in, const int* in_sizes, int n_in,
                              void* d_out, int out_size)
{
    const float* x    = (const float*)d_in[0];
    const int*   mask = (const int*)  d_in[1];
    const float* pe   = (const float*)d_in[2];
    const float* lnw  = (const float*)d_in[3];
    const float* lnb  = (const float*)d_in[4];
    const float* Wq   = (const float*)d_in[5];
    const float* bq   = (const float*)d_in[6];
    const float* Wk   = (const float*)d_in[7];
    const float* bk   = (const float*)d_in[8];
    const float* Wv   = (const float*)d_in[9];
    const float* bv   = (const float*)d_in[10];
    const float* Wa   = (const float*)d_in[11];
    const float* ba   = (const float*)d_in[12];
    const float* ra   = (const float*)d_in[13];
    const float* rm   = (const float*)d_in[14];
    float* out = (float*)d_out;

    k_prep<<<3104, 256>>>(Wq, Wk, Wv, Wa, ra, rm, x, lnw, lnb);

    dim3 g1(8, 6, 20);
    k_gemm_qkv<<<g1, 128>>>(pe, bq, bk, bv);

    dim3 gx(320, 8);
    k_xform<<<gx, 256>>>(pe);

    k_attn<<<4096, 256>>>(mask, pe);

    dim3 g2(8, 2, 20);
    k_gemm_ao<<<g2, 128>>>(pe, ba, out);
}

// round 15
// speedup vs baseline: 1.5412x; 1.5412x over previous
#include <cuda_runtime.h>
#include <math.h>
#include <stdint.h>

// ---------------- problem constants ----------------
#define BB 4
#define LL 5
#define HW 1024          // HS*WS
#define CC 256
#define MM 8
#define DD 32
#define TT 2
#define II 256           // M*D
#define NTOK (BB*LL*HW)  // 20480
#define TOKELEMS (NTOK*CC)

// K-dim permutation (within 16-groups): pos(k) = (k&~15) | ((k&3)<<2) | ((k>>2)&3)
// A thread's four fragment elements (k, k+4, k+8, k+12) become one float4.
#define PERM16(k) ((((k) & 3) << 2) | (((k) >> 2) & 3))

// ---------------- scratch (static device globals) ----------------
__device__ __align__(16) float g_xn[TOKELEMS];      // tf32 LN output, K16-permuted
__device__ __align__(16) float g_q [TOKELEMS];      // fp32 q (plain layout)
__device__ __align__(16) float g_k [TOKELEMS];      // tf32 k (plain layout)
__device__ __align__(16) float g_v [TOKELEMS];      // tf32 v (plain layout)
__device__ __align__(16) float g_kp[2*TOKELEMS];    // transformed K, ti=0/1
__device__ __align__(16) float g_vp[2*TOKELEMS];    // transformed V, ti=0/1
__device__ __align__(16) float g_ao[TOKELEMS];      // tf32 attn out, K16-permuted
__device__ __align__(16) float g_wq[TT*CC*II];      // tf32 W^T [t][n][pos16(k)]
__device__ __align__(16) float g_wk[TT*CC*II];
__device__ __align__(16) float g_wv[TT*CC*II];
__device__ __align__(16) float g_wa[TT*II*CC];
__device__ __align__(16) float g_rat[4*MM*DD*DD];   // tf32 RA*scale  [e][m][p][q]
__device__ __align__(16) float g_rmt[4*MM*DD*DD];   // tf32 RM^T      [e][m][o][p]

// ---------------- helpers ----------------
__device__ __forceinline__ unsigned f2tf(float f) {
    unsigned u;
    asm("cvt.rna.tf32.f32 %0, %1;" : "=r"(u) : "f"(f));
    return u;
}
__device__ __forceinline__ float f2tf_f(float f) { return __uint_as_float(f2tf(f)); }

__device__ __forceinline__ void mma_tf32(float c[4],
                                         unsigned a0, unsigned a1, unsigned a2, unsigned a3,
                                         unsigned b0, unsigned b1)
{
    asm volatile(
        "mma.sync.aligned.m16n8k8.row.col.f32.tf32.tf32.f32 "
        "{%0,%1,%2,%3}, {%4,%5,%6,%7}, {%8,%9}, {%0,%1,%2,%3};"
        : "+f"(c[0]), "+f"(c[1]), "+f"(c[2]), "+f"(c[3])
        : "r"(a0), "r"(a1), "r"(a2), "r"(a3), "r"(b0), "r"(b1));
}

__device__ __forceinline__ void cpa16(float* dst, const float* src) {
    unsigned d = (unsigned)__cvta_generic_to_shared(dst);
    asm volatile("cp.async.cg.shared.global [%0], [%1], 16;" :: "r"(d), "l"(src));
}
__device__ __forceinline__ void cpa_commit() {
    asm volatile("cp.async.commit_group;" ::: "memory");
}
template <int N> __device__ __forceinline__ void cpa_wait() {
    asm volatile("cp.async.wait_group %0;" :: "n"(N) : "memory");
}

// =====================================================================
// Kernel 0 (merged prep):
//   blocks [0,512)    : weight transpose + K16-perm + tf32 round
//   blocks [512,544)  : relation-matrix prep
//   blocks [544,3104) : LayerNorm (smem row-buffer, permuted store)
// (identical to R14 — PERM16 producers validated)
// =====================================================================
__global__ __launch_bounds__(256) void k_prep(const float* __restrict__ Wq,
                                              const float* __restrict__ Wk,
                                              const float* __restrict__ Wv,
                                              const float* __restrict__ Wa,
                                              const float* __restrict__ ra,
                                              const float* __restrict__ rm,
                                              const float* __restrict__ x,
                                              const float* __restrict__ lw,
                                              const float* __restrict__ lb)
{
    __shared__ float tile[32][33];
    __shared__ float slw[256], slb[256];
    __shared__ __align__(16) float rbuf[8][272];
    int bx  = blockIdx.x;
    int tid = threadIdx.x;

    if (bx < 512) {
        int tsr  = bx >> 7;
        int tt   = (bx >> 6) & 1;
        int tl   = bx & 63;
        int k0   = (tl >> 3) << 5;
        int n0   = (tl & 7) << 5;
        const float* src;
        float* dst;
        switch (tsr) {
            case 0: src = Wq; dst = g_wq; break;
            case 1: src = Wk; dst = g_wk; break;
            case 2: src = Wv; dst = g_wv; break;
            default: src = Wa; dst = g_wa; break;
        }
        src += (size_t)tt * 65536;
        dst += (size_t)tt * 65536;

        int c  = tid & 31;
        int r0 = tid >> 5;
        #pragma unroll
        for (int rr = r0; rr < 32; rr += 8)
            tile[rr][c] = src[(size_t)(k0 + rr) * 256 + n0 + c];
        __syncthreads();
        int pc = (c & 16) | PERM16(c & 15);
        #pragma unroll
        for (int rr = r0; rr < 32; rr += 8)
            dst[(size_t)(n0 + rr) * 256 + k0 + pc] = f2tf_f(tile[c][rr]);
        return;
    }

    if (bx < 544) {
        int e = (bx - 512) >> 3;
        int m = (bx - 512) & 7;
        size_t base = (size_t)(e * MM + m) * 1024;

        #pragma unroll
        for (int i = tid; i < 1024; i += 256)
            g_rat[base + i] = f2tf_f(0.17677669529663687f * ra[base + i]);

        #pragma unroll
        for (int i = tid; i < 1024; i += 256)
            tile[(i >> 5) & 31][i & 31] = rm[base + i];
        __syncthreads();
        #pragma unroll
        for (int i = tid; i < 1024; i += 256) {
            int o = i >> 5, p = i & 31;
            g_rmt[base + i] = f2tf_f(tile[p][o]);
        }
        return;
    }

    // ---- LayerNorm: one warp per token, K16-permuted store ----
    int warp = tid >> 5;
    int lane = tid & 31;
    int tok  = ((bx - 544) << 3) + warp;

    slw[tid] = lw[tid];
    slb[tid] = lb[tid];
    __syncthreads();

    const float4* xr = reinterpret_cast<const float4*>(x + (size_t)tok * CC);
    float4 v0 = xr[lane];
    float4 v1 = xr[lane + 32];
    float* rb = &rbuf[warp][0];
    reinterpret_cast<float4*>(rb)[lane]      = v0;
    reinterpret_cast<float4*>(rb)[lane + 32] = v1;
    __syncwarp();

    float val[2][4], wv[2][4], bv[2][4];
    float s = 0.f, sq = 0.f;
    #pragma unroll
    for (int h = 0; h < 2; ++h) {
        int g   = (lane >> 2) + (h << 3);
        int sub = lane & 3;
        #pragma unroll
        for (int i = 0; i < 4; ++i) {
            int k = g * 16 + (i << 2) + sub;
            float xv = rb[k];
            val[h][i] = xv;
            wv[h][i]  = slw[k];
            bv[h][i]  = slb[k];
            s  += xv;
            sq += xv * xv;
        }
    }
    #pragma unroll
    for (int off = 16; off >= 1; off >>= 1) {
        s  += __shfl_xor_sync(0xffffffffu, s,  off);
        sq += __shfl_xor_sync(0xffffffffu, sq, off);
    }
    float mean = s * (1.0f / 256.0f);
    float var  = sq * (1.0f / 256.0f) - mean * mean;
    float rstd = rsqrtf(var + 1e-5f);

    float4 o0, o1;
    o0.x = f2tf_f((val[0][0] - mean) * rstd * wv[0][0] + bv[0][0]);
    o0.y = f2tf_f((val[0][1] - mean) * rstd * wv[0][1] + bv[0][1]);
    o0.z = f2tf_f((val[0][2] - mean) * rstd * wv[0][2] + bv[0][2]);
    o0.w = f2tf_f((val[0][3] - mean) * rstd * wv[0][3] + bv[0][3]);
    o1.x = f2tf_f((val[1][0] - mean) * rstd * wv[1][0] + bv[1][0]);
    o1.y = f2tf_f((val[1][1] - mean) * rstd * wv[1][1] + bv[1][1]);
    o1.z = f2tf_f((val[1][2] - mean) * rstd * wv[1][2] + bv[1][2]);
    o1.w = f2tf_f((val[1][3] - mean) * rstd * wv[1][3] + bv[1][3]);

    float4* orow = reinterpret_cast<float4*>(g_xn + (size_t)tok * CC);
    orow[lane]      = o0;
    orow[lane + 32] = o1;
}

// =====================================================================
// tf32 GEMM tile v4: R12 warp structure (256 thr, 8 warps, 64x32/warp,
// 2 CTAs/SM) + PERM16 LDS.128 fragments + 3-stage cp.async pipeline.
// A: [m][pos16(k)] (lda=256).  Wt: [n][pos16(k)] (ld=256).
// Out[128x128] = A * Wt^T + bias.  smem = 48KB (3 x 16KB stages).
// =====================================================================
#define TSZ (128 * 16)     // 2048 floats = 8KB per tensor per stage

__device__ __forceinline__ void gemm_tf32(const float* __restrict__ A,
                                          const float* __restrict__ Wt,
                                          const float* __restrict__ bias,
                                          float* __restrict__ Out,
                                          int m0, int ncol0, int rnd)
{
    __shared__ __align__(16) float As[3 * TSZ];
    __shared__ __align__(16) float Bs[3 * TSZ];

    const int tid  = threadIdx.x;
    const int lane = tid & 31;
    const int warp = tid >> 5;
    const int wm = (warp >> 2) << 6;   // 0, 64
    const int wn = (warp & 3)  << 5;   // 0, 32, 64, 96

    // loader: 512 float4 per tensor tile / 256 threads = 2 chunks each
    int lrow[2], lc4[2];
    #pragma unroll
    for (int it = 0; it < 2; ++it) {
        int pos = tid + (it << 8);
        lrow[it] = pos >> 2;  lc4[it] = (pos & 3) << 2;
    }

    float acc[4][4][4];
    #pragma unroll
    for (int mt = 0; mt < 4; ++mt)
        #pragma unroll
        for (int nt = 0; nt < 4; ++nt)
            #pragma unroll
            for (int r = 0; r < 4; ++r) acc[mt][nt][r] = 0.0f;

    // ---- prologue: stage chunks 0 and 1 ----
    #pragma unroll
    for (int st = 0; st < 2; ++st) {
        int kc = st << 4;
        float* Asn = As + st * TSZ;
        float* Bsn = Bs + st * TSZ;
        #pragma unroll
        for (int it = 0; it < 2; ++it) {
            cpa16(Asn + lrow[it] * 16 + lc4[it],
                  A  + (size_t)(m0 + lrow[it]) * 256 + kc + lc4[it]);
            cpa16(Bsn + lrow[it] * 16 + lc4[it],
                  Wt + (size_t)(ncol0 + lrow[it]) * 256 + kc + lc4[it]);
        }
        cpa_commit();
    }

    int buf = 0;
    for (int ch = 0; ch < 16; ++ch) {
        if (ch < 14) {
            int kc  = (ch + 2) << 4;
            int nb  = buf + 2; if (nb >= 3) nb -= 3;
            float* Asn = As + nb * TSZ;
            float* Bsn = Bs + nb * TSZ;
            #pragma unroll
            for (int it = 0; it < 2; ++it) {
                cpa16(Asn + lrow[it] * 16 + lc4[it],
                      A  + (size_t)(m0 + lrow[it]) * 256 + kc + lc4[it]);
                cpa16(Bsn + lrow[it] * 16 + lc4[it],
                      Wt + (size_t)(ncol0 + lrow[it]) * 256 + kc + lc4[it]);
            }
            cpa_commit();
            cpa_wait<2>();
        } else if (ch == 14) {
            cpa_wait<1>();
        } else {
            cpa_wait<0>();
        }
        __syncthreads();

        const float* Asb = As + buf * TSZ;
        const float* Bsb = Bs + buf * TSZ;
        int kq = (lane & 3) << 2;

        // one LDS.128 per fragment row covers BOTH k-steps
        float4 af[4][2];
        float4 bf[4];
        #pragma unroll
        for (int mt = 0; mt < 4; ++mt) {
            int row = wm + (mt << 4) + (lane >> 2);
            af[mt][0] = *reinterpret_cast<const float4*>(Asb + row * 16 + kq);
            af[mt][1] = *reinterpret_cast<const float4*>(Asb + (row + 8) * 16 + kq);
        }
        #pragma unroll
        for (int nt = 0; nt < 4; ++nt) {
            int row = wn + (nt << 3) + (lane >> 2);
            bf[nt] = *reinterpret_cast<const float4*>(Bsb + row * 16 + kq);
        }
        // ks = 0 (k, k+4)
        #pragma unroll
        for (int mt = 0; mt < 4; ++mt)
            #pragma unroll
            for (int nt = 0; nt < 4; ++nt)
                mma_tf32(acc[mt][nt],
                         __float_as_uint(af[mt][0].x), __float_as_uint(af[mt][1].x),
                         __float_as_uint(af[mt][0].y), __float_as_uint(af[mt][1].y),
                         __float_as_uint(bf[nt].x),    __float_as_uint(bf[nt].y));
        // ks = 1 (k+8, k+12)
        #pragma unroll
        for (int mt = 0; mt < 4; ++mt)
            #pragma unroll
            for (int nt = 0; nt < 4; ++nt)
                mma_tf32(acc[mt][nt],
                         __float_as_uint(af[mt][0].z), __float_as_uint(af[mt][1].z),
                         __float_as_uint(af[mt][0].w), __float_as_uint(af[mt][1].w),
                         __float_as_uint(bf[nt].z),    __float_as_uint(bf[nt].w));
        __syncthreads();

        if (++buf == 3) buf = 0;
    }

    #pragma unroll
    for (int mt = 0; mt < 4; ++mt) {
        int mrow = m0 + wm + (mt << 4) + (lane >> 2);
        #pragma unroll
        for (int nt = 0; nt < 4; ++nt) {
            int nc = ncol0 + wn + (nt << 3) + ((lane & 3) << 1);
            float b0 = bias[nc], b1 = bias[nc + 1];
            float2 r0, r1;
            r0.x = acc[mt][nt][0] + b0; r0.y = acc[mt][nt][1] + b1;
            r1.x = acc[mt][nt][2] + b0; r1.y = acc[mt][nt][3] + b1;
            if (rnd) {
                r0.x = f2tf_f(r0.x); r0.y = f2tf_f(r0.y);
                r1.x = f2tf_f(r1.x); r1.y = f2tf_f(r1.y);
            }
            *reinterpret_cast<float2*>(Out + (size_t)mrow * 256 + nc)       = r0;
            *reinterpret_cast<float2*>(Out + (size_t)(mrow + 8) * 256 + nc) = r1;
        }
    }
}

// =====================================================================
// Kernel 2: q/k/v projection. grid = (8 mtiles, 6, 20 bl), 256 threads.
// =====================================================================
__global__ __launch_bounds__(256, 2) void k_gemm_qkv(const float* __restrict__ pe,
                                                     const float* __restrict__ bq,
                                                     const float* __restrict__ bk,
                                                     const float* __restrict__ bv)
{
    int bl = blockIdx.z;
    int t  = (int)pe[(size_t)bl * 3072 + 2];
    int sel   = blockIdx.y >> 1;
    int ncol0 = (blockIdx.y & 1) << 7;

    const float* W;
    const float* bias;
    float* out;
    int rnd;
    if (sel == 0)      { W = g_wq; bias = bq; out = g_q; rnd = 0; }
    else if (sel == 1) { W = g_wk; bias = bk; out = g_k; rnd = 1; }
    else               { W = g_wv; bias = bv; out = g_v; rnd = 1; }

    gemm_tf32(g_xn + (size_t)bl * HW * CC,
              W + (size_t)t * CC * II,
              bias + (size_t)t * II,
              out + (size_t)bl * HW * II,
              blockIdx.x << 7, ncol0, rnd);
}

// =====================================================================
// Kernel 2b: relation transform (unchanged — proven). grid = (320, 8).
// =====================================================================
__global__ __launch_bounds__(256) void k_xform(const float* __restrict__ pe)
{
    __shared__ __align__(16) float sra[2][32 * 36];
    __shared__ __align__(16) float srm[2][32 * 36];

    int tid  = threadIdx.x;
    int lane = tid & 31;
    int wid  = tid >> 5;
    int m    = blockIdx.y;
    int tok0 = (int)blockIdx.x << 6;
    int bl   = tok0 >> 10;
    int tj   = (int)pe[(size_t)bl * 3072 + 2];

    #pragma unroll
    for (int c = 0; c < 4; ++c) {
        int chunk = tid + (c << 8);
        int mat   = chunk >> 8;
        int off   = chunk & 255;
        int row   = off >> 3;
        int col4  = (off & 7) << 2;
        int ti    = mat & 1;
        int kind  = mat >> 1;
        const float* src = (kind ? g_rmt : g_rat)
                         + (((size_t)((ti * 2 + tj) * MM + m)) << 10) + off * 4;
        float* dst = (kind ? &srm[ti][0] : &sra[ti][0]) + row * 36 + col4;
        cpa16(dst, src);
    }
    cpa_commit();
    cpa_wait<0>();
    __syncthreads();

    int side = wid >> 2;
    int wmt  = wid & 3;
    const float* srcg = side ? g_v : g_k;
    float* dstg       = side ? g_vp : g_kp;

    int arow = tok0 + (wmt << 4) + (lane >> 2);
    const float* abase = srcg + (size_t)arow * 256 + (m << 5) + (lane & 3);
    unsigned af[4][4];
    #pragma unroll
    for (int ks = 0; ks < 4; ++ks) {
        af[ks][0] = __float_as_uint(abase[ks * 8]);
        af[ks][1] = __float_as_uint(abase[8 * 256 + ks * 8]);
        af[ks][2] = __float_as_uint(abase[ks * 8 + 4]);
        af[ks][3] = __float_as_uint(abase[8 * 256 + ks * 8 + 4]);
    }

    float acc[2][4][4];
    #pragma unroll
    for (int ti = 0; ti < 2; ++ti)
        #pragma unroll
        for (int nt = 0; nt < 4; ++nt)
            #pragma unroll
            for (int r = 0; r < 4; ++r) acc[ti][nt][r] = 0.0f;

    #pragma unroll
    for (int ks = 0; ks < 4; ++ks) {
        int k0 = (ks << 3) + (lane & 3);
        #pragma unroll
        for (int nt = 0; nt < 4; ++nt) {
            int br = (nt << 3) + (lane >> 2);
            #pragma unroll
            for (int ti = 0; ti < 2; ++ti) {
                const float* B = side ? &srm[ti][0] : &sra[ti][0];
                unsigned b0 = __float_as_uint(B[br * 36 + k0]);
                unsigned b1 = __float_as_uint(B[br * 36 + k0 + 4]);
                mma_tf32(acc[ti][nt], af[ks][0], af[ks][1], af[ks][2], af[ks][3],
                         b0, b1);
            }
        }
    }

    #pragma unroll
    for (int ti = 0; ti < 2; ++ti) {
        float* Ob = dstg + (size_t)ti * TOKELEMS;
        #pragma unroll
        for (int nt = 0; nt < 4; ++nt) {
            int col = (m << 5) + (nt << 3) + ((lane & 3) << 1);
            int r0  = tok0 + (wmt << 4) + (lane >> 2);
            float2 w0, w1;
            w0.x = acc[ti][nt][0]; w0.y = acc[ti][nt][1];
            w1.x = acc[ti][nt][2]; w1.y = acc[ti][nt][3];
            *reinterpret_cast<float2*>(Ob + (size_t)r0 * 256 + col)       = w0;
            *reinterpret_cast<float2*>(Ob + (size_t)(r0 + 8) * 256 + col) = w1;
        }
    }
}

// =====================================================================
// Kernel 3: attention. One (b,m,hw) per warp, grid = 4096.
// Output stored with K16-permuted columns (feeds ao GEMM). (= R14)
// =====================================================================
__global__ __launch_bounds__(256) void k_attn(const int*   __restrict__ mask,
                                              const float* __restrict__ pe)
{
    __shared__ int ts_s[LL];

    int tid  = threadIdx.x;
    int lane = tid & 31;
    int w    = tid >> 5;
    int bidx = blockIdx.x;
    int hw   = ((bidx & 127) << 3) + w;
    int m    = (bidx >> 7) & 7;
    int b    = bidx >> 10;

    if (tid < LL) ts_s[tid] = (int)pe[(size_t)(b * LL + tid) * 3072 + 2];
    __syncthreads();

    int base_off = (m << 5) + lane;
    int tokbase  = ((b * LL) << 10) + hw;
    float qreg[LL], kp0[LL], kp1[LL], vp0[LL], vp1[LL];
    #pragma unroll
    for (int j = 0; j < LL; ++j) {
        unsigned off = (unsigned)(tokbase + (j << 10)) * 256u + (unsigned)base_off;
        qreg[j] = g_q [off];
        kp0[j]  = g_kp[off];
        kp1[j]  = g_kp[(size_t)off + (size_t)TOKELEMS];
        vp0[j]  = g_vp[off];
        vp1[j]  = g_vp[(size_t)off + (size_t)TOKELEMS];
    }

    float att[LL][LL];
    #pragma unroll
    for (int i = 0; i < LL; ++i) {
        float q = qreg[i];
        if (ts_s[i]) {
            #pragma unroll
            for (int j = 0; j < LL; ++j) att[i][j] = q * kp1[j];
        } else {
            #pragma unroll
            for (int j = 0; j < LL; ++j) att[i][j] = q * kp0[j];
        }
        #pragma unroll
        for (int j = 0; j < LL; ++j) {
            float part = att[i][j];
            part += __shfl_xor_sync(0xffffffffu, part, 16);
            part += __shfl_xor_sync(0xffffffffu, part, 8);
            part += __shfl_xor_sync(0xffffffffu, part, 4);
            part += __shfl_xor_sync(0xffffffffu, part, 2);
            part += __shfl_xor_sync(0xffffffffu, part, 1);
            att[i][j] = part;
        }
    }

    int plane = (lane & 16) | PERM16(lane & 15);
    int obase = (m << 5) + plane;

    const int* mrow = mask + ((size_t)(b << 10) + hw) * 25;
    #pragma unroll
    for (int i = 0; i < LL; ++i) {
        float mx = -1e30f;
        #pragma unroll
        for (int j = 0; j < LL; ++j) {
            if (mrow[i * 5 + j] == 0) att[i][j] = -1e9f;
            mx = fmaxf(mx, att[i][j]);
        }
        float s = 0.f;
        #pragma unroll
        for (int j = 0; j < LL; ++j) {
            float e = __expf(att[i][j] - mx);
            att[i][j] = e;
            s += e;
        }
        float inv = 1.0f / s;
        float o = 0.f;
        if (ts_s[i]) {
            #pragma unroll
            for (int j = 0; j < LL; ++j) o = fmaf(att[i][j], vp1[j], o);
        } else {
            #pragma unroll
            for (int j = 0; j < LL; ++j) o = fmaf(att[i][j], vp0[j], o);
        }
        unsigned tok = (unsigned)(tokbase + (i << 10));
        g_ao[(size_t)tok * 256 + obase] = f2tf_f(o * inv);
    }
}

// =====================================================================
// Kernel 4: output projection + bias -> final output. grid = (8,2,20)
// =====================================================================
__global__ __launch_bounds__(256, 2) void k_gemm_ao(const float* __restrict__ pe,
                                                    const float* __restrict__ ba,
                                                    float* __restrict__ out)
{
    int bl = blockIdx.z;
    int t  = (int)pe[(size_t)bl * 3072 + 2];
    gemm_tf32(g_ao + (size_t)bl * HW * II,
              g_wa + (size_t)t * II * CC,
              ba + (size_t)t * CC,
              out + (size_t)bl * HW * CC,
              blockIdx.x << 7, (blockIdx.y & 1) << 7, 0);
}

// =====================================================================
extern "C" void kernel_launch(void* const* d_in, const int* in_sizes, int n_in,
                              void* d_out, int out_size)
{
    const float* x    = (const float*)d_in[0];
    const int*   mask = (const int*)  d_in[1];
    const float* pe   = (const float*)d_in[2];
    const float* lnw  = (const float*)d_in[3];
    const float* lnb  = (const float*)d_in[4];
    const float* Wq   = (const float*)d_in[5];
    const float* bq   = (const float*)d_in[6];
    const float* Wk   = (const float*)d_in[7];
    const float* bk   = (const float*)d_in[8];
    const float* Wv   = (const float*)d_in[9];
    const float* bv   = (const float*)d_in[10];
    const float* Wa   = (const float*)d_in[11];
    const float* ba   = (const float*)d_in[12];
    const float* ra   = (const float*)d_in[13];
    const float* rm   = (const float*)d_in[14];
    float* out = (float*)d_out;

    k_prep<<<3104, 256>>>(Wq, Wk, Wv, Wa, ra, rm, x, lnw, lnb);

    dim3 g1(8, 6, 20);
    k_gemm_qkv<<<g1, 256>>>(pe, bq, bk, bv);

    dim3 gx(320, 8);
    k_xform<<<gx, 256>>>(pe);

    k_attn<<<4096, 256>>>(mask, pe);

    dim3 g2(8, 2, 20);
    k_gemm_ao<<<g2, 256>>>(pe, ba, out);
}

// round 16
// speedup vs baseline: 1.5702x; 1.0189x over previous
#include <cuda_runtime.h>
#include <math.h>
#include <stdint.h>

// ---------------- problem constants ----------------
#define BB 4
#define LL 5
#define HW 1024          // HS*WS
#define CC 256
#define MM 8
#define DD 32
#define TT 2
#define II 256           // M*D
#define NTOK (BB*LL*HW)  // 20480
#define TOKELEMS (NTOK*CC)

// K-dim permutation: pos(k) = (k&~7) + 2*(k&3) + ((k>>2)&1)
// Makes fragment pairs (k, k+4) adjacent -> LDS.64 in the GEMM.  (= R12)
#define PERM8(c) ((((c) & 3) << 1) | (((c) >> 2) & 1))

// ---------------- scratch (static device globals) ----------------
__device__ __align__(16) float g_xn[TOKELEMS];      // tf32 LN output, K-permuted
__device__ __align__(16) float g_q [TOKELEMS];      // fp32 q (plain layout)
__device__ __align__(16) float g_k [TOKELEMS];      // tf32 k (plain layout)
__device__ __align__(16) float g_v [TOKELEMS];      // tf32 v (plain layout)
__device__ __align__(16) float g_kpv[4*TOKELEMS];   // [tok][col][{kp0,kp1,vp0,vp1}]
__device__ __align__(16) float g_ao[TOKELEMS];      // tf32 attn out, K-permuted
__device__ __align__(16) float g_wq[TT*CC*II];      // tf32 W^T [t][n][pos(k)]
__device__ __align__(16) float g_wk[TT*CC*II];
__device__ __align__(16) float g_wv[TT*CC*II];
__device__ __align__(16) float g_wa[TT*II*CC];
__device__ __align__(16) float g_rat[4*MM*DD*DD];   // tf32 RA*scale  [e][m][p][q]
__device__ __align__(16) float g_rmt[4*MM*DD*DD];   // tf32 RM^T      [e][m][o][p]

// ---------------- helpers ----------------
__device__ __forceinline__ unsigned f2tf(float f) {
    unsigned u;
    asm("cvt.rna.tf32.f32 %0, %1;" : "=r"(u) : "f"(f));
    return u;
}
__device__ __forceinline__ float f2tf_f(float f) { return __uint_as_float(f2tf(f)); }

__device__ __forceinline__ void mma_tf32(float c[4],
                                         unsigned a0, unsigned a1, unsigned a2, unsigned a3,
                                         unsigned b0, unsigned b1)
{
    asm volatile(
        "mma.sync.aligned.m16n8k8.row.col.f32.tf32.tf32.f32 "
        "{%0,%1,%2,%3}, {%4,%5,%6,%7}, {%8,%9}, {%0,%1,%2,%3};"
        : "+f"(c[0]), "+f"(c[1]), "+f"(c[2]), "+f"(c[3])
        : "r"(a0), "r"(a1), "r"(a2), "r"(a3), "r"(b0), "r"(b1));
}

__device__ __forceinline__ void cpa16(float* dst, const float* src) {
    unsigned d = (unsigned)__cvta_generic_to_shared(dst);
    asm volatile("cp.async.cg.shared.global [%0], [%1], 16;" :: "r"(d), "l"(src));
}
__device__ __forceinline__ void cpa_commit() {
    asm volatile("cp.async.commit_group;" ::: "memory");
}
template <int N> __device__ __forceinline__ void cpa_wait() {
    asm volatile("cp.async.wait_group %0;" :: "n"(N) : "memory");
}

// =====================================================================
// Kernel 0 (merged prep) — exact R12 version (PERM8 producers).
//   blocks [0,512)    : weight transpose + K-perm + tf32 round
//   blocks [512,544)  : relation-matrix prep
//   blocks [544,3104) : LayerNorm (permuted-gather, permuted store)
// =====================================================================
__global__ __launch_bounds__(256) void k_prep(const float* __restrict__ Wq,
                                              const float* __restrict__ Wk,
                                              const float* __restrict__ Wv,
                                              const float* __restrict__ Wa,
                                              const float* __restrict__ ra,
                                              const float* __restrict__ rm,
                                              const float* __restrict__ x,
                                              const float* __restrict__ lw,
                                              const float* __restrict__ lb)
{
    __shared__ float tile[32][33];
    int bx  = blockIdx.x;
    int tid = threadIdx.x;

    if (bx < 512) {
        int tsr  = bx >> 7;            // 0..3: Wq, Wk, Wv, Wa
        int tt   = (bx >> 6) & 1;      // type slice
        int tl   = bx & 63;            // 8x8 tiles of 32x32
        int k0   = (tl >> 3) << 5;
        int n0   = (tl & 7) << 5;
        const float* src;
        float* dst;
        switch (tsr) {
            case 0: src = Wq; dst = g_wq; break;
            case 1: src = Wk; dst = g_wk; break;
            case 2: src = Wv; dst = g_wv; break;
            default: src = Wa; dst = g_wa; break;
        }
        src += (size_t)tt * 65536;
        dst += (size_t)tt * 65536;

        int c  = tid & 31;
        int r0 = tid >> 5;
        #pragma unroll
        for (int rr = r0; rr < 32; rr += 8)
            tile[rr][c] = src[(size_t)(k0 + rr) * 256 + n0 + c];
        __syncthreads();
        int pc = (c & 24) | PERM8(c & 7);
        #pragma unroll
        for (int rr = r0; rr < 32; rr += 8)
            dst[(size_t)(n0 + rr) * 256 + k0 + pc] = f2tf_f(tile[c][rr]);
        return;
    }

    if (bx < 544) {
        int e = (bx - 512) >> 3;
        int m = (bx - 512) & 7;
        size_t base = (size_t)(e * MM + m) * 1024;

        #pragma unroll
        for (int i = tid; i < 1024; i += 256)
            g_rat[base + i] = f2tf_f(0.17677669529663687f * ra[base + i]);

        #pragma unroll
        for (int i = tid; i < 1024; i += 256)
            tile[(i >> 5) & 31][i & 31] = rm[base + i];
        __syncthreads();
        #pragma unroll
        for (int i = tid; i < 1024; i += 256) {
            int o = i >> 5, p = i & 31;
            g_rmt[base + i] = f2tf_f(tile[p][o]);
        }
        return;
    }

    // ---- LayerNorm: one warp per token, PERM8-permuted gather + store ----
    int warp = tid >> 5;
    int lane = tid & 31;
    int tok  = ((bx - 544) << 3) + warp;
    const float* xrow = x + (size_t)tok * CC;

    float2 xa0, xb0, xa1, xb1;
    {
        int Q0 = lane,      g0 = Q0 >> 1, q0 = Q0 & 1;
        int Q1 = lane + 32, g1 = Q1 >> 1, q1 = Q1 & 1;
        xa0 = *(const float2*)(xrow + g0 * 8 + 2 * q0);
        xb0 = *(const float2*)(xrow + g0 * 8 + 2 * q0 + 4);
        xa1 = *(const float2*)(xrow + g1 * 8 + 2 * q1);
        xb1 = *(const float2*)(xrow + g1 * 8 + 2 * q1 + 4);
    }

    float s  = xa0.x + xa0.y + xb0.x + xb0.y + xa1.x + xa1.y + xb1.x + xb1.y;
    float sq = xa0.x*xa0.x + xa0.y*xa0.y + xb0.x*xb0.x + xb0.y*xb0.y
             + xa1.x*xa1.x + xa1.y*xa1.y + xb1.x*xb1.x + xb1.y*xb1.y;
    #pragma unroll
    for (int off = 16; off >= 1; off >>= 1) {
        s  += __shfl_xor_sync(0xffffffffu, s,  off);
        sq += __shfl_xor_sync(0xffffffffu, sq, off);
    }
    float mean = s * (1.0f / 256.0f);
    float var  = sq * (1.0f / 256.0f) - mean * mean;
    float rstd = rsqrtf(var + 1e-5f);

    float2 wa0, wb0, wa1, wb1, ba0, bb0, ba1, bb1;
    {
        int Q0 = lane,      g0 = Q0 >> 1, q0 = Q0 & 1;
        int Q1 = lane + 32, g1 = Q1 >> 1, q1 = Q1 & 1;
        wa0 = *(const float2*)(lw + g0 * 8 + 2 * q0);
        wb0 = *(const float2*)(lw + g0 * 8 + 2 * q0 + 4);
        wa1 = *(const float2*)(lw + g1 * 8 + 2 * q1);
        wb1 = *(const float2*)(lw + g1 * 8 + 2 * q1 + 4);
        ba0 = *(const float2*)(lb + g0 * 8 + 2 * q0);
        bb0 = *(const float2*)(lb + g0 * 8 + 2 * q0 + 4);
        ba1 = *(const float2*)(lb + g1 * 8 + 2 * q1);
        bb1 = *(const float2*)(lb + g1 * 8 + 2 * q1 + 4);
    }

    float4 o0, o1;
    o0.x = f2tf_f((xa0.x - mean) * rstd * wa0.x + ba0.x);
    o0.y = f2tf_f((xb0.x - mean) * rstd * wb0.x + bb0.x);
    o0.z = f2tf_f((xa0.y - mean) * rstd * wa0.y + ba0.y);
    o0.w = f2tf_f((xb0.y - mean) * rstd * wb0.y + bb0.y);
    o1.x = f2tf_f((xa1.x - mean) * rstd * wa1.x + ba1.x);
    o1.y = f2tf_f((xb1.x - mean) * rstd * wb1.x + bb1.x);
    o1.z = f2tf_f((xa1.y - mean) * rstd * wa1.y + ba1.y);
    o1.w = f2tf_f((xb1.y - mean) * rstd * wb1.y + bb1.y);

    float4* orow = reinterpret_cast<float4*>(g_xn + (size_t)tok * CC);
    orow[lane]      = o0;
    orow[lane + 32] = o1;
}

// =====================================================================
// tf32 GEMM tile — exact R12 version (proven fastest config).
// 256 thr, 8 warps, 64x32/warp, BK=16 double buffer, pad-24 LDS.64.
// =====================================================================
#define TS_ST 24
#define TS_SZ (128 * TS_ST)

__device__ __forceinline__ void gemm_tf32(const float* __restrict__ A,
                                          const float* __restrict__ Wt,
                                          const float* __restrict__ bias,
                                          float* __restrict__ Out,
                                          int m0, int ncol0, int rnd)
{
    __shared__ __align__(16) float As[2 * TS_SZ];
    __shared__ __align__(16) float Bs[2 * TS_SZ];

    const int tid  = threadIdx.x;
    const int lane = tid & 31;
    const int warp = tid >> 5;
    const int wm = (warp >> 2) << 6;
    const int wn = (warp & 3)  << 5;

    int lrow[2], lc4[2];
    #pragma unroll
    for (int it = 0; it < 2; ++it) {
        int pos = tid + (it << 8);
        lrow[it] = pos >> 2;  lc4[it] = (pos & 3) << 2;
    }

    float acc[4][4][4];
    #pragma unroll
    for (int mt = 0; mt < 4; ++mt)
        #pragma unroll
        for (int nt = 0; nt < 4; ++nt)
            #pragma unroll
            for (int r = 0; r < 4; ++r) acc[mt][nt][r] = 0.0f;

    #pragma unroll
    for (int it = 0; it < 2; ++it) {
        cpa16(As + lrow[it] * TS_ST + lc4[it],
              A  + (size_t)(m0 + lrow[it]) * 256 + lc4[it]);
        cpa16(Bs + lrow[it] * TS_ST + lc4[it],
              Wt + (size_t)(ncol0 + lrow[it]) * 256 + lc4[it]);
    }
    cpa_commit();

    for (int ch = 0; ch < 16; ++ch) {
        int buf = ch & 1;
        if (ch < 15) {
            int kc = (ch + 1) << 4;
            float* Asn = As + (buf ^ 1) * TS_SZ;
            float* Bsn = Bs + (buf ^ 1) * TS_SZ;
            #pragma unroll
            for (int it = 0; it < 2; ++it) {
                cpa16(Asn + lrow[it] * TS_ST + lc4[it],
                      A  + (size_t)(m0 + lrow[it]) * 256 + kc + lc4[it]);
                cpa16(Bsn + lrow[it] * TS_ST + lc4[it],
                      Wt + (size_t)(ncol0 + lrow[it]) * 256 + kc + lc4[it]);
            }
            cpa_commit();
            cpa_wait<1>();
        } else {
            cpa_wait<0>();
        }
        __syncthreads();

        const float* Asb = As + buf * TS_SZ;
        const float* Bsb = Bs + buf * TS_SZ;

        #pragma unroll
        for (int ks = 0; ks < 2; ++ks) {
            int kp2 = (ks << 3) + ((lane & 3) << 1);
            float2 afr[4][2];
            float2 bfr[4];
            #pragma unroll
            for (int mt = 0; mt < 4; ++mt) {
                const float* pA = Asb + (wm + (mt << 4) + (lane >> 2)) * TS_ST + kp2;
                afr[mt][0] = *reinterpret_cast<const float2*>(pA);
                afr[mt][1] = *reinterpret_cast<const float2*>(pA + 8 * TS_ST);
            }
            #pragma unroll
            for (int nt = 0; nt < 4; ++nt) {
                const float* pB = Bsb + (wn + (nt << 3) + (lane >> 2)) * TS_ST + kp2;
                bfr[nt] = *reinterpret_cast<const float2*>(pB);
            }
            #pragma unroll
            for (int mt = 0; mt < 4; ++mt)
                #pragma unroll
                for (int nt = 0; nt < 4; ++nt)
                    mma_tf32(acc[mt][nt],
                             __float_as_uint(afr[mt][0].x),
                             __float_as_uint(afr[mt][1].x),
                             __float_as_uint(afr[mt][0].y),
                             __float_as_uint(afr[mt][1].y),
                             __float_as_uint(bfr[nt].x),
                             __float_as_uint(bfr[nt].y));
        }
        __syncthreads();
    }

    #pragma unroll
    for (int mt = 0; mt < 4; ++mt) {
        int mrow = m0 + wm + (mt << 4) + (lane >> 2);
        #pragma unroll
        for (int nt = 0; nt < 4; ++nt) {
            int nc = ncol0 + wn + (nt << 3) + ((lane & 3) << 1);
            float b0 = bias[nc], b1 = bias[nc + 1];
            float2 r0, r1;
            r0.x = acc[mt][nt][0] + b0; r0.y = acc[mt][nt][1] + b1;
            r1.x = acc[mt][nt][2] + b0; r1.y = acc[mt][nt][3] + b1;
            if (rnd) {
                r0.x = f2tf_f(r0.x); r0.y = f2tf_f(r0.y);
                r1.x = f2tf_f(r1.x); r1.y = f2tf_f(r1.y);
            }
            *reinterpret_cast<float2*>(Out + (size_t)mrow * 256 + nc)       = r0;
            *reinterpret_cast<float2*>(Out + (size_t)(mrow + 8) * 256 + nc) = r1;
        }
    }
}

// =====================================================================
// Kernel 2: q/k/v projection. grid = (8 mtiles, 6, 20 bl)  (= R12)
// =====================================================================
__global__ __launch_bounds__(256, 2) void k_gemm_qkv(const float* __restrict__ pe,
                                                     const float* __restrict__ bq,
                                                     const float* __restrict__ bk,
                                                     const float* __restrict__ bv)
{
    int bl = blockIdx.z;
    int t  = (int)pe[(size_t)bl * 3072 + 2];
    int sel   = blockIdx.y >> 1;
    int ncol0 = (blockIdx.y & 1) << 7;

    const float* W;
    const float* bias;
    float* out;
    int rnd;
    if (sel == 0)      { W = g_wq; bias = bq; out = g_q; rnd = 0; }
    else if (sel == 1) { W = g_wk; bias = bk; out = g_k; rnd = 1; }
    else               { W = g_wv; bias = bv; out = g_v; rnd = 1; }

    gemm_tf32(g_xn + (size_t)bl * HW * CC,
              W + (size_t)t * CC * II,
              bias + (size_t)t * II,
              out + (size_t)bl * HW * II,
              blockIdx.x << 7, ncol0, rnd);
}

// =====================================================================
// Kernel 2b: relation transform, interleaved output.
// One (128-token tile, head) per CTA: grid = (160, 8). Each warp owns 16
// token rows and computes BOTH K (RA) and V (RM) transforms for both ti,
// then writes g_kpv[tok][col][{kp0,kp1,vp0,vp1}] as contiguous float4s.
// =====================================================================
__global__ __launch_bounds__(256) void k_xform(const float* __restrict__ pe)
{
    __shared__ __align__(16) float sra[2][32 * 36];
    __shared__ __align__(16) float srm[2][32 * 36];

    int tid  = threadIdx.x;
    int lane = tid & 31;
    int wid  = tid >> 5;
    int m    = blockIdx.y;
    int tok0 = (int)blockIdx.x << 7;       // 128 tokens
    int bl   = tok0 >> 10;
    int tj   = (int)pe[(size_t)bl * 3072 + 2];

    // stage the 4 R matrices (RA ti0/1, RM^T ti0/1)
    #pragma unroll
    for (int c = 0; c < 4; ++c) {
        int chunk = tid + (c << 8);
        int mat   = chunk >> 8;
        int off   = chunk & 255;
        int row   = off >> 3;
        int col4  = (off & 7) << 2;
        int ti    = mat & 1;
        int kind  = mat >> 1;
        const float* src = (kind ? g_rmt : g_rat)
                         + (((size_t)((ti * 2 + tj) * MM + m)) << 10) + off * 4;
        float* dst = (kind ? &srm[ti][0] : &sra[ti][0]) + row * 36 + col4;
        cpa16(dst, src);
    }
    cpa_commit();
    cpa_wait<0>();
    __syncthreads();

    // A-fragments for k AND v, direct from gmem
    int arow = tok0 + (wid << 4) + (lane >> 2);
    const float* kb = g_k + (size_t)arow * 256 + (m << 5) + (lane & 3);
    const float* vb = g_v + (size_t)arow * 256 + (m << 5) + (lane & 3);
    unsigned afk[4][4], afv[4][4];
    #pragma unroll
    for (int ks = 0; ks < 4; ++ks) {
        afk[ks][0] = __float_as_uint(kb[ks * 8]);
        afk[ks][1] = __float_as_uint(kb[8 * 256 + ks * 8]);
        afk[ks][2] = __float_as_uint(kb[ks * 8 + 4]);
        afk[ks][3] = __float_as_uint(kb[8 * 256 + ks * 8 + 4]);
        afv[ks][0] = __float_as_uint(vb[ks * 8]);
        afv[ks][1] = __float_as_uint(vb[8 * 256 + ks * 8]);
        afv[ks][2] = __float_as_uint(vb[ks * 8 + 4]);
        afv[ks][3] = __float_as_uint(vb[8 * 256 + ks * 8 + 4]);
    }

    float accK[2][4][4], accV[2][4][4];
    #pragma unroll
    for (int ti = 0; ti < 2; ++ti)
        #pragma unroll
        for (int nt = 0; nt < 4; ++nt)
            #pragma unroll
            for (int r = 0; r < 4; ++r) { accK[ti][nt][r] = 0.0f; accV[ti][nt][r] = 0.0f; }

    #pragma unroll
    for (int ks = 0; ks < 4; ++ks) {
        int k0 = (ks << 3) + (lane & 3);
        #pragma unroll
        for (int nt = 0; nt < 4; ++nt) {
            int br = (nt << 3) + (lane >> 2);
            #pragma unroll
            for (int ti = 0; ti < 2; ++ti) {
                unsigned b0 = __float_as_uint(sra[ti][br * 36 + k0]);
                unsigned b1 = __float_as_uint(sra[ti][br * 36 + k0 + 4]);
                mma_tf32(accK[ti][nt], afk[ks][0], afk[ks][1], afk[ks][2], afk[ks][3], b0, b1);
                b0 = __float_as_uint(srm[ti][br * 36 + k0]);
                b1 = __float_as_uint(srm[ti][br * 36 + k0 + 4]);
                mma_tf32(accV[ti][nt], afv[ks][0], afv[ks][1], afv[ks][2], afv[ks][3], b0, b1);
            }
        }
    }

    // interleaved stores: g_kpv[tok*1024 + col*4 + {0..3}]
    #pragma unroll
    for (int nt = 0; nt < 4; ++nt) {
        int col = (m << 5) + (nt << 3) + ((lane & 3) << 1);
        float* p0 = g_kpv + (size_t)arow * 1024 + col * 4;
        float* p1 = g_kpv + (size_t)(arow + 8) * 1024 + col * 4;
        float4 w;
        w.x = accK[0][nt][0]; w.y = accK[1][nt][0]; w.z = accV[0][nt][0]; w.w = accV[1][nt][0];
        reinterpret_cast<float4*>(p0)[0] = w;
        w.x = accK[0][nt][1]; w.y = accK[1][nt][1]; w.z = accV[0][nt][1]; w.w = accV[1][nt][1];
        reinterpret_cast<float4*>(p0)[1] = w;
        w.x = accK[0][nt][2]; w.y = accK[1][nt][2]; w.z = accV[0][nt][2]; w.w = accV[1][nt][2];
        reinterpret_cast<float4*>(p1)[0] = w;
        w.x = accK[0][nt][3]; w.y = accK[1][nt][3]; w.z = accV[0][nt][3]; w.w = accV[1][nt][3];
        reinterpret_cast<float4*>(p1)[1] = w;
    }
}

// =====================================================================
// Kernel 3: attention. One (b,m,hw) per warp, grid = 4096.
// kpv gathered as 5 float4 loads (kp0,kp1,vp0,vp1 together).
// Output stored with PERM8-permuted columns (feeds ao GEMM).
// =====================================================================
__global__ __launch_bounds__(256) void k_attn(const int*   __restrict__ mask,
                                              const float* __restrict__ pe)
{
    __shared__ int ts_s[LL];

    int tid  = threadIdx.x;
    int lane = tid & 31;
    int w    = tid >> 5;
    int bidx = blockIdx.x;
    int hw   = ((bidx & 127) << 3) + w;
    int m    = (bidx >> 7) & 7;
    int b    = bidx >> 10;

    if (tid < LL) ts_s[tid] = (int)pe[(size_t)(b * LL + tid) * 3072 + 2];
    __syncthreads();

    int base_off = (m << 5) + lane;
    int tokbase  = ((b * LL) << 10) + hw;
    float qreg[LL];
    float4 kpv[LL];
    #pragma unroll
    for (int j = 0; j < LL; ++j) {
        unsigned tok = (unsigned)(tokbase + (j << 10));
        qreg[j] = g_q[(size_t)tok * 256 + base_off];
        kpv[j]  = *reinterpret_cast<const float4*>(
                      g_kpv + (size_t)tok * 1024 + (unsigned)base_off * 4);
    }

    float att[LL][LL];
    #pragma unroll
    for (int i = 0; i < LL; ++i) {
        float q = qreg[i];
        if (ts_s[i]) {
            #pragma unroll
            for (int j = 0; j < LL; ++j) att[i][j] = q * kpv[j].y;
        } else {
            #pragma unroll
            for (int j = 0; j < LL; ++j) att[i][j] = q * kpv[j].x;
        }
        #pragma unroll
        for (int j = 0; j < LL; ++j) {
            float part = att[i][j];
            part += __shfl_xor_sync(0xffffffffu, part, 16);
            part += __shfl_xor_sync(0xffffffffu, part, 8);
            part += __shfl_xor_sync(0xffffffffu, part, 4);
            part += __shfl_xor_sync(0xffffffffu, part, 2);
            part += __shfl_xor_sync(0xffffffffu, part, 1);
            att[i][j] = part;
        }
    }

    // PERM8-permuted output column for the ao GEMM (= R12)
    int plane = (lane & 24) | PERM8(lane & 7);
    int obase = (m << 5) + plane;

    const int* mrow = mask + ((size_t)(b << 10) + hw) * 25;
    #pragma unroll
    for (int i = 0; i < LL; ++i) {
        float mx = -1e30f;
        #pragma unroll
        for (int j = 0; j < LL; ++j) {
            if (mrow[i * 5 + j] == 0) att[i][j] = -1e9f;
            mx = fmaxf(mx, att[i][j]);
        }
        float s = 0.f;
        #pragma unroll
        for (int j = 0; j < LL; ++j) {
            float e = __expf(att[i][j] - mx);
            att[i][j] = e;
            s += e;
        }
        float inv = 1.0f / s;
        float o = 0.f;
        if (ts_s[i]) {
            #pragma unroll
            for (int j = 0; j < LL; ++j) o = fmaf(att[i][j], kpv[j].w, o);
        } else {
            #pragma unroll
            for (int j = 0; j < LL; ++j) o = fmaf(att[i][j], kpv[j].z, o);
        }
        unsigned tok = (unsigned)(tokbase + (i << 10));
        g_ao[(size_t)tok * 256 + obase] = f2tf_f(o * inv);
    }
}

// =====================================================================
// Kernel 4: output projection + bias -> final output. grid = (8,2,20)
// =====================================================================
__global__ __launch_bounds__(256, 2) void k_gemm_ao(const float* __restrict__ pe,
                                                    const float* __restrict__ ba,
                                                    float* __restrict__ out)
{
    int bl = blockIdx.z;
    int t  = (int)pe[(size_t)bl * 3072 + 2];
    gemm_tf32(g_ao + (size_t)bl * HW * II,
              g_wa + (size_t)t * II * CC,
              ba + (size_t)t * CC,
              out + (size_t)bl * HW * CC,
              blockIdx.x << 7, (blockIdx.y & 1) << 7, 0);
}

// =====================================================================
extern "C" void kernel_launch(void* const* d_in, const int* in_sizes, int n_in,
                              void* d_out, int out_size)
{
    const float* x    = (const float*)d_in[0];
    const int*   mask = (const int*)  d_in[1];
    const float* pe   = (const float*)d_in[2];
    const float* lnw  = (const float*)d_in[3];
    const float* lnb  = (const float*)d_in[4];
    const float* Wq   = (const float*)d_in[5];
    const float* bq   = (const float*)d_in[6];
    const float* Wk   = (const float*)d_in[7];
    const float* bk   = (const float*)d_in[8];
    const float* Wv   = (const float*)d_in[9];
    const float* bv   = (const float*)d_in[10];
    const float* Wa   = (const float*)d_in[11];
    const float* ba   = (const float*)d_in[12];
    const float* ra   = (const float*)d_in[13];
    const float* rm   = (const float*)d_in[14];
    float* out = (float*)d_out;

    k_prep<<<3104, 256>>>(Wq, Wk, Wv, Wa, ra, rm, x, lnw, lnb);

    dim3 g1(8, 6, 20);
    k_gemm_qkv<<<g1, 256>>>(pe, bq, bk, bv);

    dim3 gx(160, 8);
    k_xform<<<gx, 256>>>(pe);

    k_attn<<<4096, 256>>>(mask, pe);

    dim3 g2(8, 2, 20);
    k_gemm_ao<<<g2, 256>>>(pe, ba, out);
}